// round 1
// baseline (speedup 1.0000x reference)
#include <cuda_runtime.h>

// RenderLoss: B=262144 batches x MAXC=13 corners.
// out[b,j,:] = masked/wrapped unit normal of (next_corner - corner) projected
// onto the floor plane. y-component of the output is always 0.

constexpr int BATCH = 262144;
constexpr int MAXC  = 13;
constexpr int TPB   = 256;

constexpr int IN_F4      = TPB * MAXC * 2 / 4;   // 1664 float4 / block (26624 B)
constexpr int OUT_FLOATS = TPB * MAXC * 3;       // 9984 floats / block
constexpr int OUT_F4     = OUT_FLOATS / 4;       // 2496 float4 (39936 B)

__global__ __launch_bounds__(TPB) void render_loss_kernel(
    const float* __restrict__ gt,      // [B,13,2] lon,lat
    const int*   __restrict__ nums,    // [B]
    const float* __restrict__ ratio,   // [B]
    float*       __restrict__ out)     // [B,13,3]
{
    // One shared buffer, reused: input staging (26.6 KB) then output staging (39.9 KB).
    __shared__ float4 sm4[OUT_F4];
    float* smf = reinterpret_cast<float*>(sm4);

    const int t = threadIdx.x;
    const int b = blockIdx.x * TPB + t;

    // ---- Phase 1: coalesced input stage (float4) ----
    const float4* gin = reinterpret_cast<const float4*>(
        gt + (size_t)blockIdx.x * TPB * MAXC * 2);
    #pragma unroll
    for (int i = 0; i < 7; i++) {
        int idx = t + i * TPB;
        if (idx < IN_F4) sm4[idx] = gin[idx];
    }
    const int   num = nums[b];
    const float h   = -1.6f * ratio[b];   // s = h / sin(lat)
    __syncthreads();

    // Copy this thread's 13 (lon,lat) pairs to registers (stride 13 floats*2:
    // lane stride 26 -> 2-way smem conflict max, cheap).
    float2 c[MAXC];
    #pragma unroll
    for (int j = 0; j < MAXC; j++) {
        c[j].x = smf[(t * MAXC + j) * 2 + 0];   // lon
        c[j].y = smf[(t * MAXC + j) * 2 + 1];   // lat
    }
    __syncthreads();   // input area about to be overwritten by output staging

    // ---- Phase 2: compute ----
    auto corner = [&](float2 ll, float& x, float& z) {
        float sl, cl, so, co;
        __sincosf(ll.y, &sl, &cl);   // lat
        __sincosf(ll.x, &so, &co);   // lon
        float s = __fdividef(h, sl); // h/sin(lat); |sin(lat)| >= 0.199
        x = cl * so * s;
        z = cl * co * s;
    };

    float x0, z0;
    corner(c[0], x0, z0);
    float curx = x0, curz = z0;
    float n0x = 0.f, n0z = 0.f;

    float* ob = smf + t * (MAXC * 3);   // lane stride 39 (odd) -> conflict-free STS

    #pragma unroll
    for (int j = 0; j < MAXC; j++) {
        float xn = 0.f, zn = 0.f;
        if (j + 1 < MAXC) corner(c[j + 1], xn, zn);

        const bool last  = (j + 1 == num);       // wrap to corner 0
        const bool valid = (j < num);

        float tx = last ? x0 : xn;
        float tz = last ? z0 : zn;

        float vx = valid ? (tx - curx) : 1.0f;   // invalid -> vec=(1,0,0)
        float vz = valid ? (tz - curz) : 0.0f;

        float rn = rsqrtf(vx * vx + vz * vz);
        float nx = -vz * rn;
        float nz =  vx * rn;

        if (j == 0) { n0x = nx; n0z = nz; }      // num>=4 so j=0 is always valid

        float ox = 0.f, oz = 0.f;
        if (valid)         { ox = nx;  oz = nz;  }
        else if (j == num) { ox = n0x; oz = n0z; } // wrap row copies normal of edge 0

        ob[3 * j + 0] = ox;
        ob[3 * j + 1] = 0.0f;
        ob[3 * j + 2] = oz;

        curx = xn; curz = zn;
    }
    __syncthreads();

    // ---- Phase 3: coalesced output store (float4) ----
    float4* gout = reinterpret_cast<float4*>(
        out + (size_t)blockIdx.x * OUT_FLOATS);
    #pragma unroll
    for (int i = 0; i < 10; i++) {
        int idx = t + i * TPB;
        if (idx < OUT_F4) gout[idx] = sm4[idx];
    }
}

extern "C" void kernel_launch(void* const* d_in, const int* in_sizes, int n_in,
                              void* d_out, int out_size)
{
    const float* gt    = (const float*)d_in[0];  // GT_up [B,13,2] f32
    const int*   nums  = (const int*)  d_in[1];  // corner_nums [B] i32
    const float* ratio = (const float*)d_in[2];  // up_down_ratio [B] f32
    float*       out   = (float*)d_out;          // [B,13,3] f32

    render_loss_kernel<<<BATCH / TPB, TPB>>>(gt, nums, ratio, out);
}

// round 2
// speedup vs baseline: 1.1600x; 1.1600x over previous
#include <cuda_runtime.h>

// RenderLoss: B=262144 batches x MAXC=13 corners.
// out[b,j,:] = masked/wrapped unit normal of (next_corner - corner) projected
// onto the floor plane. y-component of the output is always 0.
//
// R2: cut smem 40KB -> 26.6KB (output staged in two 128-batch halves, each a
// contiguous global range) so 8 blocks/SM fit -> 64 warps theoretical occupancy.

constexpr int BATCH = 262144;
constexpr int MAXC  = 13;
constexpr int TPB   = 256;

constexpr int IN_F4       = TPB * MAXC * 2 / 4;   // 1664 float4 (26624 B)
constexpr int HALF_FLOATS = 128 * MAXC * 3;       // 4992 floats (19968 B)
constexpr int HALF_F4     = HALF_FLOATS / 4;      // 1248 float4
constexpr int SM_F4       = IN_F4;                // buffer = max(in, out-half)

__global__ __launch_bounds__(TPB) void render_loss_kernel(
    const float* __restrict__ gt,      // [B,13,2] lon,lat
    const int*   __restrict__ nums,    // [B]
    const float* __restrict__ ratio,   // [B]
    float*       __restrict__ out)     // [B,13,3]
{
    __shared__ float4 sm4[SM_F4];
    float* smf = reinterpret_cast<float*>(sm4);

    const int t = threadIdx.x;
    const int b = blockIdx.x * TPB + t;

    // ---- Phase 1: coalesced input stage (float4) ----
    const float4* gin = reinterpret_cast<const float4*>(
        gt + (size_t)blockIdx.x * TPB * MAXC * 2);
    #pragma unroll
    for (int i = 0; i < 7; i++) {
        int idx = t + i * TPB;
        if (idx < IN_F4) sm4[idx] = gin[idx];
    }
    const int   num = nums[b];
    const float h   = -1.6f * ratio[b];   // s = h / sin(lat)
    __syncthreads();

    // This thread's 13 (lon,lat) pairs -> registers.
    float2 c[MAXC];
    #pragma unroll
    for (int j = 0; j < MAXC; j++) {
        c[j].x = smf[(t * MAXC + j) * 2 + 0];   // lon
        c[j].y = smf[(t * MAXC + j) * 2 + 1];   // lat
    }

    // ---- Phase 2: compute all 13 output normals into registers ----
    auto corner = [&](float2 ll, float& x, float& z) {
        float sl, cl, so, co;
        __sincosf(ll.y, &sl, &cl);   // lat
        __sincosf(ll.x, &so, &co);   // lon
        float s = __fdividef(h, sl); // |sin(lat)| >= 0.199 -> well-conditioned
        x = cl * so * s;
        z = cl * co * s;
    };

    float ox[MAXC], oz[MAXC];

    float x0, z0;
    corner(c[0], x0, z0);
    float curx = x0, curz = z0;
    float n0x = 0.f, n0z = 0.f;

    #pragma unroll
    for (int j = 0; j < MAXC; j++) {
        float xn = 0.f, zn = 0.f;
        if (j + 1 < MAXC) corner(c[j + 1], xn, zn);

        const bool last  = (j + 1 == num);       // wrap edge back to corner 0
        const bool valid = (j < num);

        float tx = last ? x0 : xn;
        float tz = last ? z0 : zn;

        float vx = valid ? (tx - curx) : 1.0f;   // invalid -> vec=(1,0,0)
        float vz = valid ? (tz - curz) : 0.0f;

        float rn = rsqrtf(vx * vx + vz * vz);
        float nx = -vz * rn;
        float nz =  vx * rn;

        if (j == 0) { n0x = nx; n0z = nz; }      // num>=4 so j=0 always valid

        float px = 0.f, pz = 0.f;
        if (valid)         { px = nx;  pz = nz;  }
        else if (j == num) { px = n0x; pz = n0z; } // wrap row = normal of edge 0

        ox[j] = px;
        oz[j] = pz;

        curx = xn; curz = zn;
    }

    // ---- Phase 3: output in two 128-batch halves (each contiguous in gmem) ----
    const int my_half = t >> 7;       // 0 or 1
    const int tl      = t & 127;      // index within half
    float* gob = out + (size_t)blockIdx.x * (TPB * MAXC * 3);

    #pragma unroll
    for (int half = 0; half < 2; half++) {
        __syncthreads();              // buffer free (input regs read / prev store done)
        if (my_half == half) {
            float* obuf = smf + tl * (MAXC * 3);  // stride 39 (odd) -> conflict-free
            #pragma unroll
            for (int j = 0; j < MAXC; j++) {
                obuf[3 * j + 0] = ox[j];
                obuf[3 * j + 1] = 0.0f;
                obuf[3 * j + 2] = oz[j];
            }
        }
        __syncthreads();
        float4* gout = reinterpret_cast<float4*>(gob + half * HALF_FLOATS);
        #pragma unroll
        for (int i = 0; i < 5; i++) {
            int idx = t + i * TPB;
            if (idx < HALF_F4) gout[idx] = sm4[idx];
        }
    }
}

extern "C" void kernel_launch(void* const* d_in, const int* in_sizes, int n_in,
                              void* d_out, int out_size)
{
    const float* gt    = (const float*)d_in[0];  // GT_up [B,13,2] f32
    const int*   nums  = (const int*)  d_in[1];  // corner_nums [B] i32
    const float* ratio = (const float*)d_in[2];  // up_down_ratio [B] f32
    float*       out   = (float*)d_out;          // [B,13,3] f32

    render_loss_kernel<<<BATCH / TPB, TPB>>>(gt, nums, ratio, out);
}